// round 17
// baseline (speedup 1.0000x reference)
#include <cuda_runtime.h>
#include <cuda_fp16.h>
#include <math.h>
#include <stdint.h>

#define NV   65536
#define CC   64
#define HH   4
#define DD   16
#define KV   125
#define PP   1048576

// Scratch (device globals; zero-initialized at module load)
__device__ float  g_nq[NV * CC];
__device__ __half g_kv[NV * 128];    // per row: 16 lanes x (k0..k3, v0..v3)
__device__ __half g_npos_h[KV * CC];
__device__ __half g_wo_h[CC * CC];   // Wo^T fp16
__device__ int    g_cnt[NV];         // zero before hist; zeroed again by offsets
__device__ int    g_off[NV + 1];
__device__ int    g_bsum[64];
__device__ int    g_rank[PP];
__device__ int    g_sorted[PP];

__device__ __forceinline__ float4 ldh4(const __half* p)
{
    const uint2 u = *(const uint2*)p;
    const __half2 a = *reinterpret_cast<const __half2*>(&u.x);
    const __half2 b = *reinterpret_cast<const __half2*>(&u.y);
    const float2 fa = __half22float2(a);
    const float2 fb = __half22float2(b);
    return make_float4(fa.x, fa.y, fb.x, fb.y);
}
__device__ __forceinline__ void unph8(uint4 u, float4& lo, float4& hi)
{
    const __half2 a = *reinterpret_cast<const __half2*>(&u.x);
    const __half2 b = *reinterpret_cast<const __half2*>(&u.y);
    const __half2 c = *reinterpret_cast<const __half2*>(&u.z);
    const __half2 d = *reinterpret_cast<const __half2*>(&u.w);
    const float2 fa = __half22float2(a);
    const float2 fb = __half22float2(b);
    const float2 fc = __half22float2(c);
    const float2 fd = __half22float2(d);
    lo = make_float4(fa.x, fa.y, fb.x, fb.y);
    hi = make_float4(fc.x, fc.y, fd.x, fd.y);
}

// ---------------------------------------------------------------------------
// qkv via mma.sync (HMMA m16n8k16), fp16 inputs, fp32 accum.
// ---------------------------------------------------------------------------
#define XH_STRIDE 72
#define QKV_SMEM  (128 * 72 * 2 + 3 * 64 * 72 * 2 + 3 * 64 * 4)

__global__ void __launch_bounds__(256) qkv_mma_kernel(
    const float* __restrict__ x,
    const float* __restrict__ Wq, const float* __restrict__ bq,
    const float* __restrict__ Wk, const float* __restrict__ bk,
    const float* __restrict__ Wv, const float* __restrict__ bv)
{
    extern __shared__ __half sh[];
    __half* xh = sh;                       // [128][72]
    __half* wt = sh + 128 * XH_STRIDE;     // [3][64][72]
    float*  sBias = (float*)(sh + 128 * XH_STRIDE + 3 * 64 * XH_STRIDE);

    const int tid = threadIdx.x;
    const int rowBase = blockIdx.x * 128;

    {
        const float4* xg = (const float4*)(x + (size_t)rowBase * CC);
#pragma unroll
        for (int i = 0; i < 8; i++) {
            const int idx = i * 256 + tid;
            const int row = idx >> 4;
            const int c4  = (idx & 15) * 4;
            const float4 v = xg[idx];
            const __half2 h0 = __floats2half2_rn(v.x, v.y);
            const __half2 h1 = __floats2half2_rn(v.z, v.w);
            uint2 u;
            u.x = *reinterpret_cast<const unsigned*>(&h0);
            u.y = *reinterpret_cast<const unsigned*>(&h1);
            *(uint2*)&xh[row * XH_STRIDE + c4] = u;
        }
    }
    {
        const float* Ws[3] = {Wq, Wk, Wv};
#pragma unroll
        for (int m = 0; m < 3; m++) {
            const float* W = Ws[m];
            __half* wm = wt + m * 64 * XH_STRIDE;
#pragma unroll
            for (int i = 0; i < 16; i++) {
                const int idx = i * 256 + tid;
                const int k = idx >> 6;
                const int n = idx & 63;
                wm[n * XH_STRIDE + k] = __float2half(W[idx]);
            }
        }
    }
    if (tid < 64) {
        sBias[tid]       = bq[tid];
        sBias[64 + tid]  = bk[tid];
        sBias[128 + tid] = bv[tid];
    }
    __syncthreads();

    const int lane = tid & 31;
    const int wid  = tid >> 5;
    const int g    = lane >> 2;
    const int tg   = lane & 3;
    const int r0   = wid * 16;

    uint32_t a[4][4];
#pragma unroll
    for (int ks = 0; ks < 4; ks++) {
        const int kc = ks * 16 + 2 * tg;
        a[ks][0] = *(const uint32_t*)&xh[(r0 + g)     * XH_STRIDE + kc];
        a[ks][1] = *(const uint32_t*)&xh[(r0 + g + 8) * XH_STRIDE + kc];
        a[ks][2] = *(const uint32_t*)&xh[(r0 + g)     * XH_STRIDE + kc + 8];
        a[ks][3] = *(const uint32_t*)&xh[(r0 + g + 8) * XH_STRIDE + kc + 8];
    }

    const int rA = rowBase + r0 + g;
    const int rB = rA + 8;

#pragma unroll
    for (int m = 0; m < 3; m++) {
        float c[8][4];
#pragma unroll
        for (int j = 0; j < 8; j++) {
            c[j][0] = 0.f; c[j][1] = 0.f; c[j][2] = 0.f; c[j][3] = 0.f;
            const __half* wrow = wt + m * 64 * XH_STRIDE + (j * 8 + g) * XH_STRIDE;
#pragma unroll
            for (int ks = 0; ks < 4; ks++) {
                const uint32_t b0 = *(const uint32_t*)&wrow[ks * 16 + 2 * tg];
                const uint32_t b1 = *(const uint32_t*)&wrow[ks * 16 + 2 * tg + 8];
                asm volatile(
                    "mma.sync.aligned.m16n8k16.row.col.f32.f16.f16.f32 "
                    "{%0,%1,%2,%3}, {%4,%5,%6,%7}, {%8,%9}, {%0,%1,%2,%3};"
                    : "+f"(c[j][0]), "+f"(c[j][1]), "+f"(c[j][2]), "+f"(c[j][3])
                    : "r"(a[ks][0]), "r"(a[ks][1]), "r"(a[ks][2]), "r"(a[ks][3]),
                      "r"(b0), "r"(b1));
            }
            const float bf0 = sBias[m * 64 + j * 8 + 2 * tg];
            const float bf1 = sBias[m * 64 + j * 8 + 2 * tg + 1];
            c[j][0] += bf0; c[j][1] += bf1;
            c[j][2] += bf0; c[j][3] += bf1;
        }

        if (m < 2) {
#pragma unroll
            for (int h = 0; h < 4; h++) {
                float sA = c[2*h][0]*c[2*h][0] + c[2*h][1]*c[2*h][1]
                         + c[2*h+1][0]*c[2*h+1][0] + c[2*h+1][1]*c[2*h+1][1];
                float sB = c[2*h][2]*c[2*h][2] + c[2*h][3]*c[2*h][3]
                         + c[2*h+1][2]*c[2*h+1][2] + c[2*h+1][3]*c[2*h+1][3];
                sA += __shfl_xor_sync(0xffffffffu, sA, 1, 4);
                sB += __shfl_xor_sync(0xffffffffu, sB, 1, 4);
                sA += __shfl_xor_sync(0xffffffffu, sA, 2, 4);
                sB += __shfl_xor_sync(0xffffffffu, sB, 2, 4);
                const float invA = 1.0f / fmaxf(sqrtf(sA), 1e-12f);
                const float invB = 1.0f / fmaxf(sqrtf(sB), 1e-12f);
                c[2*h][0] *= invA; c[2*h][1] *= invA;
                c[2*h+1][0] *= invA; c[2*h+1][1] *= invA;
                c[2*h][2] *= invB; c[2*h][3] *= invB;
                c[2*h+1][2] *= invB; c[2*h+1][3] *= invB;
            }
        }

        if (m == 0) {
#pragma unroll
            for (int j = 0; j < 8; j++) {
                const int col = j * 8 + 2 * tg;
                *(float2*)&g_nq[(size_t)rA * CC + col] = make_float2(c[j][0], c[j][1]);
                *(float2*)&g_nq[(size_t)rB * CC + col] = make_float2(c[j][2], c[j][3]);
            }
        } else {
            const int off = (m == 1) ? 0 : 4;
#pragma unroll
            for (int j = 0; j < 8; j++) {
                const int col  = j * 8 + 2 * tg;
                const int slot = col >> 2;
                const int pos  = col & 3;
                const __half2 hA = __floats2half2_rn(c[j][0], c[j][1]);
                const __half2 hB = __floats2half2_rn(c[j][2], c[j][3]);
                *(__half2*)&g_kv[(size_t)rA * 128 + slot * 8 + pos + off] = hA;
                *(__half2*)&g_kv[(size_t)rB * 128 + slot * 8 + pos + off] = hB;
            }
        }
    }
}

// ---------------------------------------------------------------------------
// Histogram of out_idx + per-pair rank (atomic return value), side stream
// ---------------------------------------------------------------------------
__global__ void __launch_bounds__(256) hist_kernel(const int* __restrict__ kq)
{
    const int t = blockIdx.x * 256 + threadIdx.x;   // 0 .. PP/2-1
    const int2 o = ((const int2*)(kq + PP))[t];
    const int r0 = atomicAdd(&g_cnt[o.x], 1);
    const int r1 = atomicAdd(&g_cnt[o.y], 1);
    ((int2*)g_rank)[t] = make_int2(r0, r1);
}

// ---------------------------------------------------------------------------
// Scan stage A + pos-enc normalize + Wo^T fp16 conversion
// ---------------------------------------------------------------------------
__global__ void __launch_bounds__(256) blocksum_kernel(
    const float* __restrict__ pe, const float* __restrict__ Wo)
{
    __shared__ int ssum[8];
    const int t = threadIdx.x;
    const int4 c = ((const int4*)g_cnt)[blockIdx.x * 256 + t];
    int s = c.x + c.y + c.z + c.w;
#pragma unroll
    for (int o = 16; o > 0; o >>= 1) s += __shfl_xor_sync(0xffffffffu, s, o);
    if ((t & 31) == 0) ssum[t >> 5] = s;

    if (t < 128) {
        const int row = blockIdx.x * 8 + (t >> 4);
        if (row < KV * HH) {
            const int ch = t & 15;
            const float v = pe[row * DD + ch];
            float ss = v * v;
            ss += __shfl_xor_sync(0xffffffffu, ss, 1, 16);
            ss += __shfl_xor_sync(0xffffffffu, ss, 2, 16);
            ss += __shfl_xor_sync(0xffffffffu, ss, 4, 16);
            ss += __shfl_xor_sync(0xffffffffu, ss, 8, 16);
            const float inv = 1.0f / fmaxf(sqrtf(ss), 1e-12f);
            g_npos_h[row * DD + ch] = __float2half(v * inv);
        }
    }
    {
        const int idx = blockIdx.x * 256 + t;
        if (idx < CC * CC) {
            const int n = idx >> 6;
            const int k = idx & 63;
            g_wo_h[idx] = __float2half(Wo[k * CC + n]);
        }
    }

    __syncthreads();
    if (t < 8) {
        int v = ssum[t];
#pragma unroll
        for (int o = 4; o > 0; o >>= 1) v += __shfl_xor_sync(0xffu, v, o, 8);
        if (t == 0) g_bsum[blockIdx.x] = v;
    }
}

// ---------------------------------------------------------------------------
// Scan stage B: writes g_off and zeroes g_cnt (restores replay invariant).
// ---------------------------------------------------------------------------
__global__ void __launch_bounds__(256) offsets_kernel()
{
    __shared__ int swarp[8];
    __shared__ int sbase;
    const int t = threadIdx.x;
    const int gi = blockIdx.x * 256 + t;
    const int4 c = ((const int4*)g_cnt)[gi];
    const int s = c.x + c.y + c.z + c.w;

    if (t < 32) {
        const int B = blockIdx.x;
        int v = 0;
        if (t < B)      v += g_bsum[t];
        if (t + 32 < B) v += g_bsum[t + 32];
#pragma unroll
        for (int o = 16; o > 0; o >>= 1) v += __shfl_xor_sync(0xffffffffu, v, o);
        if (t == 0) sbase = v;
    }

    int inc = s;
#pragma unroll
    for (int o = 1; o < 32; o <<= 1) {
        int v = __shfl_up_sync(0xffffffffu, inc, o);
        if ((t & 31) >= o) inc += v;
    }
    if ((t & 31) == 31) swarp[t >> 5] = inc;
    __syncthreads();
    if (t < 8) {
        int v = swarp[t];
#pragma unroll
        for (int o = 1; o < 8; o <<= 1) {
            int u = __shfl_up_sync(0xffu, v, o, 8);
            if (t >= o) v += u;
        }
        swarp[t] = v;
    }
    __syncthreads();
    int excl = inc - s;
    if (t >= 32) excl += swarp[(t >> 5) - 1];
    excl += sbase;

    int4 off;
    off.x = excl;
    off.y = off.x + c.x;
    off.z = off.y + c.y;
    off.w = off.z + c.z;
    ((int4*)g_off)[gi] = off;
    ((int4*)g_cnt)[gi] = make_int4(0, 0, 0, 0);
    if (gi == NV / 4 - 1) g_off[NV] = PP;
}

// ---------------------------------------------------------------------------
// Scatter: atomic-free — pos = off[o] + rank[p].
// ---------------------------------------------------------------------------
__global__ void __launch_bounds__(256) scatter_kernel(const int* __restrict__ kq)
{
    const int t = blockIdx.x * 256 + threadIdx.x;   // 0 .. PP/2-1
    const int2 a = ((const int2*)kq)[t];
    const int2 o = ((const int2*)(kq + PP))[t];
    const int2 r = ((const int2*)g_rank)[t];

    const int p0 = g_off[o.x] + r.x;
    const int p1 = g_off[o.y] + r.y;

    int ini, kx;
    ini = a.x / KV; kx = a.x - ini * KV; g_sorted[p0] = (ini << 7) | kx;
    ini = a.y / KV; kx = a.y - ini * KV; g_sorted[p1] = (ini << 7) | kx;
}

// ---------------------------------------------------------------------------
// Fused gather + output GEMM + residual. 512 threads, 16 voxels/block,
// ONE voxel per warp (no Poisson imbalance, no main-loop predicates).
// Half h of each warp processes pairs i+2m+h of its voxel's segment.
// ---------------------------------------------------------------------------
__global__ void __launch_bounds__(512) gather_out_kernel(
    const float* __restrict__ bo, const float* __restrict__ x,
    float* __restrict__ out)
{
    __shared__ __half ah[16 * XH_STRIDE];
    __shared__ __half wt[64 * XH_STRIDE];
    __shared__ float  sBias[64];

    const int tid   = threadIdx.x;
    const int lane  = tid & 31;
    const int warp  = tid >> 5;          // 0..15 = voxel within block
    const int voxel = blockIdx.x * 16 + warp;
    const int h     = lane >> 4;         // half
    const int l16   = lane & 15;
    const int c4    = l16 * 4;

    // load Wo^T tile (4096 halves = 512 uint4; exactly one per thread)
    {
        const uint4* w4 = (const uint4*)g_wo_h;
        *(uint4*)&wt[(tid >> 3) * XH_STRIDE + (tid & 7) * 8] = w4[tid];
    }
    if (tid < 64) sBias[tid] = bo[tid];

    // ---- Phase 1: gather ----
    const int beg = g_off[voxel];
    const int n   = g_off[voxel + 1] - beg;

    const float4 q = *(const float4*)&g_nq[(size_t)voxel * CC + c4];
    float4 accA = make_float4(0.f, 0.f, 0.f, 0.f);
    float4 accB = make_float4(0.f, 0.f, 0.f, 0.f);

    int sval = (lane < n) ? g_sorted[beg + lane] : 0;

    for (int base = 0; base < n; base += 32) {
        const int nextIdx = base + 32 + lane;
        const int svalNext = (nextIdx < n) ? g_sorted[beg + nextIdx] : 0;
        const int chunk = min(32, n - base);

        int i = 0;
        for (; i + 7 < chunk; i += 8) {
            // half h handles pairs i+2m+h (m=0..3); all < chunk -> no predicates
            const int s0 = __shfl_sync(0xffffffffu, sval, i + 0 + h, 32);
            const int s1 = __shfl_sync(0xffffffffu, sval, i + 2 + h, 32);
            const int s2 = __shfl_sync(0xffffffffu, sval, i + 4 + h, 32);
            const int s3 = __shfl_sync(0xffffffffu, sval, i + 6 + h, 32);

            const uint4 kv0 = *(const uint4*)&g_kv[(size_t)(s0 >> 7) * 128 + l16 * 8];
            const uint4 kv1 = *(const uint4*)&g_kv[(size_t)(s1 >> 7) * 128 + l16 * 8];
            const uint4 kv2 = *(const uint4*)&g_kv[(size_t)(s2 >> 7) * 128 + l16 * 8];
            const uint4 kv3 = *(const uint4*)&g_kv[(size_t)(s3 >> 7) * 128 + l16 * 8];
            const float4 e0 = ldh4(&g_npos_h[(s0 & 127) * CC + c4]);
            const float4 e1 = ldh4(&g_npos_h[(s1 & 127) * CC + c4]);
            const float4 e2 = ldh4(&g_npos_h[(s2 & 127) * CC + c4]);
            const float4 e3 = ldh4(&g_npos_h[(s3 & 127) * CC + c4]);

            float4 k0, w0, k1, w1, k2, w2, k3, w3;
            unph8(kv0, k0, w0);
            unph8(kv1, k1, w1);
            unph8(kv2, k2, w2);
            unph8(kv3, k3, w3);

            float t0 = (k0.x + e0.x) * q.x + (k0.y + e0.y) * q.y
                     + (k0.z + e0.z) * q.z + (k0.w + e0.w) * q.w;
            float t1 = (k1.x + e1.x) * q.x + (k1.y + e1.y) * q.y
                     + (k1.z + e1.z) * q.z + (k1.w + e1.w) * q.w;
            float t2 = (k2.x + e2.x) * q.x + (k2.y + e2.y) * q.y
                     + (k2.z + e2.z) * q.z + (k2.w + e2.w) * q.w;
            float t3 = (k3.x + e3.x) * q.x + (k3.y + e3.y) * q.y
                     + (k3.z + e3.z) * q.z + (k3.w + e3.w) * q.w;

            t0 += __shfl_xor_sync(0xffffffffu, t0, 1, 4);
            t1 += __shfl_xor_sync(0xffffffffu, t1, 1, 4);
            t2 += __shfl_xor_sync(0xffffffffu, t2, 1, 4);
            t3 += __shfl_xor_sync(0xffffffffu, t3, 1, 4);
            t0 += __shfl_xor_sync(0xffffffffu, t0, 2, 4);
            t1 += __shfl_xor_sync(0xffffffffu, t1, 2, 4);
            t2 += __shfl_xor_sync(0xffffffffu, t2, 2, 4);
            t3 += __shfl_xor_sync(0xffffffffu, t3, 2, 4);

            accA.x = fmaf(t0, w0.x, accA.x);
            accA.y = fmaf(t0, w0.y, accA.y);
            accA.z = fmaf(t0, w0.z, accA.z);
            accA.w = fmaf(t0, w0.w, accA.w);
            accB.x = fmaf(t1, w1.x, accB.x);
            accB.y = fmaf(t1, w1.y, accB.y);
            accB.z = fmaf(t1, w1.z, accB.z);
            accB.w = fmaf(t1, w1.w, accB.w);
            accA.x = fmaf(t2, w2.x, accA.x);
            accA.y = fmaf(t2, w2.y, accA.y);
            accA.z = fmaf(t2, w2.z, accA.z);
            accA.w = fmaf(t2, w2.w, accA.w);
            accB.x = fmaf(t3, w3.x, accB.x);
            accB.y = fmaf(t3, w3.y, accB.y);
            accB.z = fmaf(t3, w3.z, accB.z);
            accB.w = fmaf(t3, w3.w, accB.w);
        }
        // tail: pairs i+h, step 2, with predicate
        for (; i < chunk; i += 2) {
            const int idx = i + h;
            const bool valid = idx < chunk;
            const int src = valid ? idx : 0;
            const int s0 = __shfl_sync(0xffffffffu, sval, src, 32);
            const uint4 kv0 = *(const uint4*)&g_kv[(size_t)(s0 >> 7) * 128 + l16 * 8];
            const float4 e0 = ldh4(&g_npos_h[(s0 & 127) * CC + c4]);
            float4 k0, w0;
            unph8(kv0, k0, w0);
            float t0 = (k0.x + e0.x) * q.x + (k0.y + e0.y) * q.y
                     + (k0.z + e0.z) * q.z + (k0.w + e0.w) * q.w;
            t0 += __shfl_xor_sync(0xffffffffu, t0, 1, 4);
            t0 += __shfl_xor_sync(0xffffffffu, t0, 2, 4);
            if (!valid) t0 = 0.f;
            accA.x = fmaf(t0, w0.x, accA.x);
            accA.y = fmaf(t0, w0.y, accA.y);
            accA.z = fmaf(t0, w0.z, accA.z);
            accA.w = fmaf(t0, w0.w, accA.w);
        }
        sval = svalNext;
    }

    // combine the two halves (lane l and l^16 hold same channels)
    float4 acc = make_float4(accA.x + accB.x, accA.y + accB.y,
                             accA.z + accB.z, accA.w + accB.w);
    acc.x += __shfl_xor_sync(0xffffffffu, acc.x, 16, 32);
    acc.y += __shfl_xor_sync(0xffffffffu, acc.y, 16, 32);
    acc.z += __shfl_xor_sync(0xffffffffu, acc.z, 16, 32);
    acc.w += __shfl_xor_sync(0xffffffffu, acc.w, 16, 32);

    if (h == 0) {
        const __half2 h0 = __floats2half2_rn(acc.x, acc.y);
        const __half2 h1 = __floats2half2_rn(acc.z, acc.w);
        uint2 u;
        u.x = *reinterpret_cast<const unsigned*>(&h0);
        u.y = *reinterpret_cast<const unsigned*>(&h1);
        *(uint2*)&ah[warp * XH_STRIDE + c4] = u;
    }
    __syncthreads();

    // ---- Phase 2: out = acc @ Wo + bo + x (warps 0..7, one n-tile each) ----
    if (warp < 8) {
        const int g  = lane >> 2;
        const int tg = lane & 3;

        uint32_t a[4][4];
#pragma unroll
        for (int ks = 0; ks < 4; ks++) {
            const int kc = ks * 16 + 2 * tg;
            a[ks][0] = *(const uint32_t*)&ah[g       * XH_STRIDE + kc];
            a[ks][1] = *(const uint32_t*)&ah[(g + 8) * XH_STRIDE + kc];
            a[ks][2] = *(const uint32_t*)&ah[g       * XH_STRIDE + kc + 8];
            a[ks][3] = *(const uint32_t*)&ah[(g + 8) * XH_STRIDE + kc + 8];
        }

        float c[4] = {0.f, 0.f, 0.f, 0.f};
        const __half* wrow = wt + (warp * 8 + g) * XH_STRIDE;
#pragma unroll
        for (int ks = 0; ks < 4; ks++) {
            const uint32_t b0 = *(const uint32_t*)&wrow[ks * 16 + 2 * tg];
            const uint32_t b1 = *(const uint32_t*)&wrow[ks * 16 + 2 * tg + 8];
            asm volatile(
                "mma.sync.aligned.m16n8k16.row.col.f32.f16.f16.f32 "
                "{%0,%1,%2,%3}, {%4,%5,%6,%7}, {%8,%9}, {%0,%1,%2,%3};"
                : "+f"(c[0]), "+f"(c[1]), "+f"(c[2]), "+f"(c[3])
                : "r"(a[ks][0]), "r"(a[ks][1]), "r"(a[ks][2]), "r"(a[ks][3]),
                  "r"(b0), "r"(b1));
        }

        const int col = warp * 8 + 2 * tg;
        const int rA  = blockIdx.x * 16 + g;
        const int rB  = rA + 8;
        const float bf0 = sBias[col];
        const float bf1 = sBias[col + 1];
        const float2 xA = *(const float2*)&x[(size_t)rA * CC + col];
        const float2 xB = *(const float2*)&x[(size_t)rB * CC + col];
        *(float2*)&out[(size_t)rA * CC + col] = make_float2(c[0] + bf0 + xA.x, c[1] + bf1 + xA.y);
        *(float2*)&out[(size_t)rB * CC + col] = make_float2(c[2] + bf0 + xB.x, c[3] + bf1 + xB.y);
    }
}

// ---------------------------------------------------------------------------
extern "C" void kernel_launch(void* const* d_in, const int* in_sizes, int n_in,
                              void* d_out, int out_size)
{
    const float* x  = (const float*)d_in[0];
    const float* Wq = (const float*)d_in[1];
    const float* bq = (const float*)d_in[2];
    const float* Wk = (const float*)d_in[3];
    const float* bk = (const float*)d_in[4];
    const float* Wv = (const float*)d_in[5];
    const float* bv = (const float*)d_in[6];
    const float* Wo = (const float*)d_in[7];
    const float* bo = (const float*)d_in[8];
    const float* pe = (const float*)d_in[9];
    const int*   kq = (const int*)d_in[10];
    float* out = (float*)d_out;

    cudaFuncSetAttribute(qkv_mma_kernel, cudaFuncAttributeMaxDynamicSharedMemorySize, QKV_SMEM);

    cudaStream_t sB;
    cudaStreamCreateWithFlags(&sB, cudaStreamNonBlocking);
    cudaEvent_t evFork, evJoin;
    cudaEventCreateWithFlags(&evFork, cudaEventDisableTiming);
    cudaEventCreateWithFlags(&evJoin, cudaEventDisableTiming);

    cudaEventRecord(evFork, 0);
    cudaStreamWaitEvent(sB, evFork, 0);

    // side stream: hist(+rank) -> scan -> offsets(+cnt reset) -> scatter
    hist_kernel<<<PP / 2 / 256, 256, 0, sB>>>(kq);
    blocksum_kernel<<<64, 256, 0, sB>>>(pe, Wo);
    offsets_kernel<<<64, 256, 0, sB>>>();
    scatter_kernel<<<PP / 2 / 256, 256, 0, sB>>>(kq);
    cudaEventRecord(evJoin, sB);

    // main stream: HMMA QKV
    qkv_mma_kernel<<<NV / 128, 256, QKV_SMEM>>>(x, Wq, bq, Wk, bk, Wv, bv);

    cudaStreamWaitEvent(0, evJoin, 0);
    gather_out_kernel<<<NV / 16, 512>>>(bo, x, out);
}